// round 9
// baseline (speedup 1.0000x reference)
#include <cuda_runtime.h>
#include <cuda_bf16.h>

#define NN 50000
#define NE 800000
#define NG 128
#define F 64
#define CAP 64    // max stored in-degree; deg ~ Poisson(16), P(>64) ~ 1e-18

// ---- scratch (static device arrays; no allocation) ----
__device__ __align__(16) float g_xp[NN * F];    // x @ W (current layer)
__device__ __align__(16) float g_h[NN * F];     // finalized layer output
__device__ float g_asrc[NN];
__device__ float g_adst[NN];
__device__ float g_denom[NN];                   // self-loop exp
__device__ __align__(16) float g_pool[NG * F];
__device__ int g_gcnt[NG];
__device__ int g_deg[NN];
__device__ int g_csr[NN * CAP];                 // src lists grouped by dst
__device__ float g_w[NN * CAP];                 // edge weights, same layout
__device__ int g_slot[NE];                      // edge -> csr slot

__global__ void zero_kernel() {
    int i = blockIdx.x * blockDim.x + threadIdx.x;
    if (i < NG * F) g_pool[i] = 0.f;
    if (i < NG) g_gcnt[i] = 0;
    if (i < NN) g_deg[i] = 0;
}

// Build by-dst adjacency + slot map + per-graph node counts. Once per launch.
__global__ __launch_bounds__(256) void build_kernel(
    const int* __restrict__ src, const int* __restrict__ dst,
    const int* __restrict__ batch)
{
    int t = blockIdx.x * blockDim.x + threadIdx.x;

    if (t < NN / 4) {
        int4 b4 = ((const int4*)batch)[t];
        atomicAdd(&g_gcnt[b4.x], 1);
        atomicAdd(&g_gcnt[b4.y], 1);
        atomicAdd(&g_gcnt[b4.z], 1);
        atomicAdd(&g_gcnt[b4.w], 1);
    }

    if (t >= NE / 4) return;
    int4 s4 = ((const int4*)src)[t];
    int4 d4 = ((const int4*)dst)[t];
    int4 sl = make_int4(-1, -1, -1, -1);
    int r;
    r = atomicAdd(&g_deg[d4.x], 1); if (r < CAP) { g_csr[d4.x * CAP + r] = s4.x; sl.x = d4.x * CAP + r; }
    r = atomicAdd(&g_deg[d4.y], 1); if (r < CAP) { g_csr[d4.y * CAP + r] = s4.y; sl.y = d4.y * CAP + r; }
    r = atomicAdd(&g_deg[d4.z], 1); if (r < CAP) { g_csr[d4.z * CAP + r] = s4.z; sl.z = d4.z * CAP + r; }
    r = atomicAdd(&g_deg[d4.w], 1); if (r < CAP) { g_csr[d4.w * CAP + r] = s4.w; sl.w = d4.w * CAP + r; }
    ((int4*)g_slot)[t] = sl;
}

// Edge-parallel attention weights: w = exp(leaky(asrc[s] + adst[d])) -> g_w[slot].
// Coalesced edge reads, huge parallelism; hides the random asrc/adst gathers.
__global__ __launch_bounds__(256) void weight_kernel(
    const int* __restrict__ src, const int* __restrict__ dst)
{
    int t = blockIdx.x * blockDim.x + threadIdx.x;
    if (t >= NE / 4) return;
    int4 s4 = ((const int4*)src)[t];
    int4 d4 = ((const int4*)dst)[t];
    int4 sl = ((const int4*)g_slot)[t];

    float e0 = g_asrc[s4.x] + g_adst[d4.x];
    float e1 = g_asrc[s4.y] + g_adst[d4.y];
    float e2 = g_asrc[s4.z] + g_adst[d4.z];
    float e3 = g_asrc[s4.w] + g_adst[d4.w];
    e0 = e0 > 0.f ? e0 : 0.2f * e0;
    e1 = e1 > 0.f ? e1 : 0.2f * e1;
    e2 = e2 > 0.f ? e2 : 0.2f * e2;
    e3 = e3 > 0.f ? e3 : 0.2f * e3;
    if (sl.x >= 0) g_w[sl.x] = __expf(e0);
    if (sl.y >= 0) g_w[sl.y] = __expf(e1);
    if (sl.z >= 0) g_w[sl.z] = __expf(e2);
    if (sl.w >= 0) g_w[sl.w] = __expf(e3);
}

// Node kernel (register-tiled GEMM, 4 nodes/thread):
// 256 threads handle 64 nodes. Thread (g = tid>>4, c = tid&15) computes
// nodes {g, g+16, g+32, g+48}, features [4c, 4c+4).
__global__ __launch_bounds__(256) void node_kernel(
    const float* __restrict__ x,          // used if use_x
    const float* __restrict__ W,
    const float* __restrict__ a_src,
    const float* __restrict__ a_dst,
    int use_x)                            // else read finalized g_h
{
    __shared__ float4 Wsm[F * 16];   // [k][c] : W[k][4c..4c+3]
    __shared__ float hsm[64 * 65];   // [node][k], padded stride 65

    int tid = threadIdx.x;
    const float4* W4 = (const float4*)W;
    for (int i = tid; i < F * 16; i += 256) Wsm[i] = W4[i];

    int c = tid & 15;
    int g = tid >> 4;
    int base = blockIdx.x * 64;

    float4 as4 = ((const float4*)a_src)[c];
    float4 ad4 = ((const float4*)a_dst)[c];

    // ---- stage h for 64 nodes ----
    const float4* hin = use_x ? (const float4*)x : (const float4*)g_h;
    for (int i = tid; i < 1024; i += 256) {
        int node = i >> 4, cc = i & 15;
        int n = base + node;
        float4 v = make_float4(0.f, 0.f, 0.f, 0.f);
        if (n < NN) v = hin[n * 16 + cc];
        float* hp = &hsm[node * 65 + cc * 4];
        hp[0] = v.x; hp[1] = v.y; hp[2] = v.z; hp[3] = v.w;
    }
    __syncthreads();

    // ---- GEMM: xp[n][f] = sum_k h[n][k] * W[k][f] ----
    float4 acc0 = make_float4(0.f,0.f,0.f,0.f);
    float4 acc1 = make_float4(0.f,0.f,0.f,0.f);
    float4 acc2 = make_float4(0.f,0.f,0.f,0.f);
    float4 acc3 = make_float4(0.f,0.f,0.f,0.f);
    const float* h0 = &hsm[(g     ) * 65];
    const float* h1 = &hsm[(g + 16) * 65];
    const float* h2 = &hsm[(g + 32) * 65];
    const float* h3 = &hsm[(g + 48) * 65];
#pragma unroll
    for (int k = 0; k < F; ++k) {
        float4 w = Wsm[k * 16 + c];
        float a0 = h0[k], a1 = h1[k], a2 = h2[k], a3 = h3[k];
        acc0.x = fmaf(a0, w.x, acc0.x); acc0.y = fmaf(a0, w.y, acc0.y);
        acc0.z = fmaf(a0, w.z, acc0.z); acc0.w = fmaf(a0, w.w, acc0.w);
        acc1.x = fmaf(a1, w.x, acc1.x); acc1.y = fmaf(a1, w.y, acc1.y);
        acc1.z = fmaf(a1, w.z, acc1.z); acc1.w = fmaf(a1, w.w, acc1.w);
        acc2.x = fmaf(a2, w.x, acc2.x); acc2.y = fmaf(a2, w.y, acc2.y);
        acc2.z = fmaf(a2, w.z, acc2.z); acc2.w = fmaf(a2, w.w, acc2.w);
        acc3.x = fmaf(a3, w.x, acc3.x); acc3.y = fmaf(a3, w.y, acc3.y);
        acc3.z = fmaf(a3, w.z, acc3.z); acc3.w = fmaf(a3, w.w, acc3.w);
    }

    float4 accs[4] = {acc0, acc1, acc2, acc3};
#pragma unroll
    for (int r = 0; r < 4; ++r) {
        float4 a = accs[r];
        float ps = a.x * as4.x + a.y * as4.y + a.z * as4.z + a.w * as4.w;
        float pd = a.x * ad4.x + a.y * ad4.y + a.z * ad4.z + a.w * ad4.w;
#pragma unroll
        for (int o = 1; o < 16; o <<= 1) {
            ps += __shfl_xor_sync(0xffffffffu, ps, o, 16);
            pd += __shfl_xor_sync(0xffffffffu, pd, o, 16);
        }
        int n = base + g + 16 * r;
        if (n < NN) {
            if (c == 0) {
                g_asrc[n] = ps; g_adst[n] = pd;
                float e = ps + pd; e = e > 0.f ? e : 0.2f * e;   // self-loop logit
                g_denom[n] = __expf(e);
            }
            ((float4*)g_xp)[n * 16 + c] = a;
        }
    }
}

// Aggregation + epilogue: one warp per node, float2 per lane.
// (s, w) come from uniform broadcast loads (L1-resident rows); dsum accumulates
// identically in all lanes -> no reductions, no shfl, no smem, no sync.
// Batches of 8 gathers (float2) = 16 result regs -> MLP 8 at high occupancy.
// FINAL=0: write h = relu(total/denom + bias) to g_h.
// FINAL=1: graph-mean pool via red.v2 into g_pool.
template<int FINAL>
__global__ __launch_bounds__(256) void agg_kernel(
    const float* __restrict__ bias, const int* __restrict__ batch)
{
    int n = (blockIdx.x * 256 + threadIdx.x) >> 5;
    int lane = threadIdx.x & 31;
    if (n >= NN) return;

    int deg = min(g_deg[n], CAP);
    float exs = g_denom[n];
    const int* row = &g_csr[n * CAP];
    const float* wrow = &g_w[n * CAP];
    const float2* xp2 = (const float2*)g_xp;

    float2 sv = xp2[n * 32 + lane];
    float2 acc = make_float2(exs * sv.x, exs * sv.y);
    float dsum = exs;   // uniform across lanes

    for (int j0 = 0; j0 < deg; j0 += 8) {
        int s[8]; float w[8];
#pragma unroll
        for (int i = 0; i < 8; ++i) {
            int jj = j0 + i;
            bool ok = jj < deg;
            s[i] = ok ? row[jj] : n;     // uniform broadcast load
            w[i] = ok ? wrow[jj] : 0.f;  // uniform broadcast load
        }
        float2 v[8];
#pragma unroll
        for (int i = 0; i < 8; ++i)
            v[i] = xp2[(unsigned)s[i] * 32u + (unsigned)lane];
#pragma unroll
        for (int i = 0; i < 8; ++i) {
            acc.x = fmaf(w[i], v[i].x, acc.x);
            acc.y = fmaf(w[i], v[i].y, acc.y);
            dsum += w[i];
        }
    }

    float dinv = 1.f / dsum;
    float2 b = ((const float2*)bias)[lane];
    float2 h;
    h.x = fmaxf(fmaf(acc.x, dinv, b.x), 0.f);
    h.y = fmaxf(fmaf(acc.y, dinv, b.y), 0.f);

    if (FINAL) {
        int g = batch[n];
        float* addr = g_pool + (g * 32 + lane) * 2;
        asm volatile("red.global.add.v2.f32 [%0], {%1,%2};"
                     :: "l"(addr), "f"(h.x), "f"(h.y) : "memory");
    } else {
        ((float2*)g_h)[n * 32 + lane] = h;
    }
}

__global__ void final_kernel(float* __restrict__ out) {
    int i = blockIdx.x * blockDim.x + threadIdx.x;
    if (i >= NG * F) return;
    int g = i >> 6;
    float c = (float)max(g_gcnt[g], 1);
    out[i] = g_pool[i] / c;
}

extern "C" void kernel_launch(void* const* d_in, const int* in_sizes, int n_in,
                              void* d_out, int out_size) {
    const float* x     = (const float*)d_in[0];
    const int*   ei    = (const int*)d_in[1];     // [2, NE]
    const int*   batch = (const int*)d_in[2];
    const float* W1    = (const float*)d_in[3];
    const float* as1   = (const float*)d_in[4];
    const float* ad1   = (const float*)d_in[5];
    const float* b1    = (const float*)d_in[6];
    const float* W2    = (const float*)d_in[7];
    const float* as2   = (const float*)d_in[8];
    const float* ad2   = (const float*)d_in[9];
    const float* b2    = (const float*)d_in[10];
    float* out = (float*)d_out;

    const int* src = ei;
    const int* dst = ei + NE;

    int node_blocks  = (NN + 63) / 64;            // 782
    int agg_blocks   = (NN * 32 + 255) / 256;     // 6250
    int edge4_blocks = (NE / 4 + 255) / 256;      // 782

    zero_kernel<<<(NN + 255) / 256, 256>>>();
    build_kernel<<<edge4_blocks, 256>>>(src, dst, batch);

    // layer 1
    node_kernel<<<node_blocks, 256>>>(x, W1, as1, ad1, 1);
    weight_kernel<<<edge4_blocks, 256>>>(src, dst);
    agg_kernel<0><<<agg_blocks, 256>>>(b1, batch);

    // layer 2 (agg fuses relu+bias+graph-pool)
    node_kernel<<<node_blocks, 256>>>(nullptr, W2, as2, ad2, 0);
    weight_kernel<<<edge4_blocks, 256>>>(src, dst);
    agg_kernel<1><<<agg_blocks, 256>>>(b2, batch);

    final_kernel<<<(NG * F + 255) / 256, 256>>>(out);
}

// round 10
// speedup vs baseline: 1.2371x; 1.2371x over previous
#include <cuda_runtime.h>
#include <cuda_bf16.h>
#include <cuda_fp16.h>

#define NN 50000
#define NE 800000
#define NG 128
#define F 64
#define CAP 64    // max stored in-degree; deg ~ Poisson(16), P(>64) ~ 1e-18

// ---- scratch (static device arrays; no allocation) ----
__device__ __align__(16) __half g_xp[NN * F];   // x @ W, fp16 values (logits stay fp32)
__device__ __align__(16) float g_h[NN * F];     // finalized layer output (fp32)
__device__ float g_asrc[NN];
__device__ float g_adst[NN];
__device__ float g_denom[NN];                   // self-loop exp
__device__ __align__(16) float g_pool[NG * F];
__device__ int g_gcnt[NG];
__device__ int g_deg[NN];
__device__ int g_csr[NN * CAP];                 // src lists grouped by dst

__device__ __forceinline__ void red_add_v4(float* addr, float a, float b, float c, float d) {
    asm volatile("red.global.add.v4.f32 [%0], {%1,%2,%3,%4};"
                 :: "l"(addr), "f"(a), "f"(b), "f"(c), "f"(d) : "memory");
}

__global__ void zero_kernel() {
    int i = blockIdx.x * blockDim.x + threadIdx.x;
    if (i < NG * F) g_pool[i] = 0.f;
    if (i < NG) g_gcnt[i] = 0;
    if (i < NN) g_deg[i] = 0;
}

// Build by-dst adjacency + per-graph node counts. Once per launch.
__global__ __launch_bounds__(256) void build_kernel(
    const int* __restrict__ src, const int* __restrict__ dst,
    const int* __restrict__ batch)
{
    int t = blockIdx.x * blockDim.x + threadIdx.x;

    if (t < NN / 4) {
        int4 b4 = ((const int4*)batch)[t];
        atomicAdd(&g_gcnt[b4.x], 1);
        atomicAdd(&g_gcnt[b4.y], 1);
        atomicAdd(&g_gcnt[b4.z], 1);
        atomicAdd(&g_gcnt[b4.w], 1);
    }

    if (t >= NE / 4) return;
    int4 s4 = ((const int4*)src)[t];
    int4 d4 = ((const int4*)dst)[t];
    int r;
    r = atomicAdd(&g_deg[d4.x], 1); if (r < CAP) g_csr[d4.x * CAP + r] = s4.x;
    r = atomicAdd(&g_deg[d4.y], 1); if (r < CAP) g_csr[d4.y * CAP + r] = s4.y;
    r = atomicAdd(&g_deg[d4.z], 1); if (r < CAP) g_csr[d4.z * CAP + r] = s4.z;
    r = atomicAdd(&g_deg[d4.w], 1); if (r < CAP) g_csr[d4.w * CAP + r] = s4.w;
}

// Node kernel (register-tiled GEMM, 4 nodes/thread):
// 256 threads handle 64 nodes. Thread (g = tid>>4, c = tid&15) computes
// nodes {g, g+16, g+32, g+48}, features [4c, 4c+4).
// Logits (asrc/adst/denom) computed in fp32; xp stored fp16.
__global__ __launch_bounds__(256) void node_kernel(
    const float* __restrict__ x,          // used if use_x
    const float* __restrict__ W,
    const float* __restrict__ a_src,
    const float* __restrict__ a_dst,
    int use_x)                            // else read finalized g_h
{
    __shared__ float4 Wsm[F * 16];   // [k][c] : W[k][4c..4c+3]
    __shared__ float hsm[64 * 65];   // [node][k], padded stride 65

    int tid = threadIdx.x;
    const float4* W4 = (const float4*)W;
    for (int i = tid; i < F * 16; i += 256) Wsm[i] = W4[i];

    int c = tid & 15;
    int g = tid >> 4;
    int base = blockIdx.x * 64;

    float4 as4 = ((const float4*)a_src)[c];
    float4 ad4 = ((const float4*)a_dst)[c];

    // ---- stage h for 64 nodes ----
    const float4* hin = use_x ? (const float4*)x : (const float4*)g_h;
    for (int i = tid; i < 1024; i += 256) {
        int node = i >> 4, cc = i & 15;
        int n = base + node;
        float4 v = make_float4(0.f, 0.f, 0.f, 0.f);
        if (n < NN) v = hin[n * 16 + cc];
        float* hp = &hsm[node * 65 + cc * 4];
        hp[0] = v.x; hp[1] = v.y; hp[2] = v.z; hp[3] = v.w;
    }
    __syncthreads();

    // ---- GEMM: xp[n][f] = sum_k h[n][k] * W[k][f] ----
    float4 acc0 = make_float4(0.f,0.f,0.f,0.f);
    float4 acc1 = make_float4(0.f,0.f,0.f,0.f);
    float4 acc2 = make_float4(0.f,0.f,0.f,0.f);
    float4 acc3 = make_float4(0.f,0.f,0.f,0.f);
    const float* h0 = &hsm[(g     ) * 65];
    const float* h1 = &hsm[(g + 16) * 65];
    const float* h2 = &hsm[(g + 32) * 65];
    const float* h3 = &hsm[(g + 48) * 65];
#pragma unroll
    for (int k = 0; k < F; ++k) {
        float4 w = Wsm[k * 16 + c];
        float a0 = h0[k], a1 = h1[k], a2 = h2[k], a3 = h3[k];
        acc0.x = fmaf(a0, w.x, acc0.x); acc0.y = fmaf(a0, w.y, acc0.y);
        acc0.z = fmaf(a0, w.z, acc0.z); acc0.w = fmaf(a0, w.w, acc0.w);
        acc1.x = fmaf(a1, w.x, acc1.x); acc1.y = fmaf(a1, w.y, acc1.y);
        acc1.z = fmaf(a1, w.z, acc1.z); acc1.w = fmaf(a1, w.w, acc1.w);
        acc2.x = fmaf(a2, w.x, acc2.x); acc2.y = fmaf(a2, w.y, acc2.y);
        acc2.z = fmaf(a2, w.z, acc2.z); acc2.w = fmaf(a2, w.w, acc2.w);
        acc3.x = fmaf(a3, w.x, acc3.x); acc3.y = fmaf(a3, w.y, acc3.y);
        acc3.z = fmaf(a3, w.z, acc3.z); acc3.w = fmaf(a3, w.w, acc3.w);
    }

    float4 accs[4] = {acc0, acc1, acc2, acc3};
#pragma unroll
    for (int r = 0; r < 4; ++r) {
        float4 a = accs[r];
        float ps = a.x * as4.x + a.y * as4.y + a.z * as4.z + a.w * as4.w;
        float pd = a.x * ad4.x + a.y * ad4.y + a.z * ad4.z + a.w * ad4.w;
#pragma unroll
        for (int o = 1; o < 16; o <<= 1) {
            ps += __shfl_xor_sync(0xffffffffu, ps, o, 16);
            pd += __shfl_xor_sync(0xffffffffu, pd, o, 16);
        }
        int n = base + g + 16 * r;
        if (n < NN) {
            if (c == 0) {
                g_asrc[n] = ps; g_adst[n] = pd;
                float e = ps + pd; e = e > 0.f ? e : 0.2f * e;   // self-loop logit
                g_denom[n] = __expf(e);
            }
            __half2 p0 = __floats2half2_rn(a.x, a.y);
            __half2 p1 = __floats2half2_rn(a.z, a.w);
            uint2 u;
            u.x = *reinterpret_cast<unsigned*>(&p0);
            u.y = *reinterpret_cast<unsigned*>(&p1);
            ((uint2*)g_xp)[n * 16 + c] = u;
        }
    }
}

// Aggregation + epilogue: 16 lanes per dst node, 16 nodes per 256-thread block.
// Phase A: lanes compute (src, ex) in fp32, stage in smem (float2).
// Phase B: batches of 8 edges; each gather is LDG.64 (4 halves) -> low register
//          cost lets ptxas keep several loads in flight at high occupancy.
// FINAL=0: write h = relu(total/denom + bias) to g_h (fp32).
// FINAL=1: graph-mean pool via red.v4 into g_pool.
template<int FINAL>
__global__ __launch_bounds__(256) void agg_kernel(
    const float* __restrict__ bias, const int* __restrict__ batch)
{
    __shared__ float2 stage[16][CAP];   // [group][edge] = (bitcast src, ex)

    int gid = blockIdx.x * blockDim.x + threadIdx.x;
    int n = gid >> 4;
    int grp = threadIdx.x >> 4;         // 0..15
    int lane = threadIdx.x & 15;
    unsigned gmask = 0xFFFFu << (threadIdx.x & 16);
    if (n >= NN) return;

    int deg = min(g_deg[n], CAP);
    float adstn = g_adst[n];
    float ex_self = g_denom[n];
    const int* row = &g_csr[n * CAP];
    const uint2* xp2 = (const uint2*)g_xp;   // 4 halves per lane

    // ---- Phase A: stage (src, ex), accumulate per-lane dsum ----
    float dsum = 0.f;
    for (int j = lane; j < deg; j += 16) {
        int s = row[j];
        float e = g_asrc[s] + adstn;
        e = e > 0.f ? e : 0.2f * e;
        float ex = __expf(e);
        dsum += ex;
        stage[grp][j] = make_float2(__int_as_float(s), ex);
    }
    __syncwarp();

    // self-loop feature contribution (weight added once after lane-reduction)
    uint2 su = xp2[n * 16 + lane];
    float2 s0 = __half22float2(*reinterpret_cast<__half2*>(&su.x));
    float2 s1 = __half22float2(*reinterpret_cast<__half2*>(&su.y));
    float4 acc = make_float4(ex_self * s0.x, ex_self * s0.y,
                             ex_self * s1.x, ex_self * s1.y);

    // ---- Phase B: batched fp16 gather ----
    for (int j0 = 0; j0 < deg; j0 += 8) {
        float2 e[8];
#pragma unroll
        for (int i = 0; i < 8; ++i) {
            int jj = j0 + i < deg ? j0 + i : 0;   // clamp; weight zeroed below
            e[i] = stage[grp][jj];
            if (j0 + i >= deg) e[i].y = 0.f;
        }
        uint2 v[8];
#pragma unroll
        for (int i = 0; i < 8; ++i)
            v[i] = xp2[(unsigned)__float_as_int(e[i].x) * 16u + (unsigned)lane];
#pragma unroll
        for (int i = 0; i < 8; ++i) {
            float2 a0 = __half22float2(*reinterpret_cast<__half2*>(&v[i].x));
            float2 a1 = __half22float2(*reinterpret_cast<__half2*>(&v[i].y));
            acc.x = fmaf(e[i].y, a0.x, acc.x);
            acc.y = fmaf(e[i].y, a0.y, acc.y);
            acc.z = fmaf(e[i].y, a1.x, acc.z);
            acc.w = fmaf(e[i].y, a1.y, acc.w);
        }
    }

#pragma unroll
    for (int o = 1; o < 16; o <<= 1)
        dsum += __shfl_xor_sync(gmask, dsum, o, 16);
    dsum += ex_self;    // self weight counted exactly once

    float dinv = 1.f / dsum;
    float4 b = ((const float4*)bias)[lane];
    float4 h;
    h.x = fmaxf(fmaf(acc.x, dinv, b.x), 0.f);
    h.y = fmaxf(fmaf(acc.y, dinv, b.y), 0.f);
    h.z = fmaxf(fmaf(acc.z, dinv, b.z), 0.f);
    h.w = fmaxf(fmaf(acc.w, dinv, b.w), 0.f);

    if (FINAL) {
        int g = batch[n];
        red_add_v4(g_pool + (g * 16 + lane) * 4, h.x, h.y, h.z, h.w);
    } else {
        ((float4*)g_h)[n * 16 + lane] = h;
    }
}

__global__ void final_kernel(float* __restrict__ out) {
    int i = blockIdx.x * blockDim.x + threadIdx.x;
    if (i >= NG * F) return;
    int g = i >> 6;
    float c = (float)max(g_gcnt[g], 1);
    out[i] = g_pool[i] / c;
}

extern "C" void kernel_launch(void* const* d_in, const int* in_sizes, int n_in,
                              void* d_out, int out_size) {
    const float* x     = (const float*)d_in[0];
    const int*   ei    = (const int*)d_in[1];     // [2, NE]
    const int*   batch = (const int*)d_in[2];
    const float* W1    = (const float*)d_in[3];
    const float* as1   = (const float*)d_in[4];
    const float* ad1   = (const float*)d_in[5];
    const float* b1    = (const float*)d_in[6];
    const float* W2    = (const float*)d_in[7];
    const float* as2   = (const float*)d_in[8];
    const float* ad2   = (const float*)d_in[9];
    const float* b2    = (const float*)d_in[10];
    float* out = (float*)d_out;

    const int* src = ei;
    const int* dst = ei + NE;

    int node_blocks  = (NN + 63) / 64;            // 782
    int agg_blocks   = (NN * 16 + 255) / 256;     // 3125
    int edge4_blocks = (NE / 4 + 255) / 256;      // 782

    zero_kernel<<<(NN + 255) / 256, 256>>>();
    build_kernel<<<edge4_blocks, 256>>>(src, dst, batch);

    // layer 1
    node_kernel<<<node_blocks, 256>>>(x, W1, as1, ad1, 1);
    agg_kernel<0><<<agg_blocks, 256>>>(b1, batch);

    // layer 2 (agg fuses relu+bias+graph-pool)
    node_kernel<<<node_blocks, 256>>>(nullptr, W2, as2, ad2, 0);
    agg_kernel<1><<<agg_blocks, 256>>>(b2, batch);

    final_kernel<<<(NG * F + 255) / 256, 256>>>(out);
}